// round 2
// baseline (speedup 1.0000x reference)
#include <cuda_runtime.h>
#include <cuda_bf16.h>

// Problem constants (fixed by setup_inputs)
#define RES     64
#define N_PHAL  20
#define BATCH   256
#define N_PIX   (RES * RES)        // 4096
#define CH      5
#define CHUNK   256                // pixels staged per iteration
#define NCHUNK  (N_PIX / CHUNK)    // 16
#define F4_PER_CHUNK (CHUNK * CH / 4)  // 320 float4 per chunk

// Scratch: per (b, p): [denom, vf0_sum, vf1_sum, vs0_sum, vs1_sum]
__device__ float g_scratch[BATCH * N_PHAL * 5];

// ---------------------------------------------------------------------------
// Kernel 1: per-(b,p) spatial reduction.
// grid = (N_PHAL, BATCH), block = 256 threads.
// Double-buffered SMEM staging: while chunk c is consumed from buffer c&1,
// chunk c+1's coalesced float4 loads are in flight into buffer (c+1)&1.
// Thread t consumes pixel t of the chunk via stride-5 LDS (conflict-free,
// gcd(5,32)==1).
// ---------------------------------------------------------------------------
__global__ __launch_bounds__(256) void reduce_kernel(const float* __restrict__ x)
{
    __shared__ float s[2][CHUNK * CH];     // 2 x 5120 bytes
    __shared__ float red[8][5];

    const int p = blockIdx.x;
    const int b = blockIdx.y;
    const int t = threadIdx.x;

    const float4* __restrict__ base =
        (const float4*)(x + (size_t)(b * N_PHAL + p) * (size_t)(N_PIX * CH));

    float den = 0.f, vf0 = 0.f, vf1 = 0.f, vs0 = 0.f, vs1 = 0.f;

    // Prologue: stage chunk 0
    {
        const float4* __restrict__ src = base;
        ((float4*)s[0])[t] = src[t];
        if (t < F4_PER_CHUNK - 256)
            ((float4*)s[0])[256 + t] = src[256 + t];
    }

    #pragma unroll 1
    for (int c = 0; c < NCHUNK; ++c) {
        const int cur = c & 1, nxt = cur ^ 1;
        __syncthreads();   // chunk c staged; buffer nxt free (consumed 2 iters ago)

        // Kick off next chunk's loads into the other buffer (overlaps consume)
        if (c + 1 < NCHUNK) {
            const float4* __restrict__ src = base + (c + 1) * F4_PER_CHUNK;
            ((float4*)s[nxt])[t] = src[t];
            if (t < F4_PER_CHUNK - 256)
                ((float4*)s[nxt])[256 + t] = src[256 + t];
        }

        // Consume pixel t of chunk c
        const float f0 = s[cur][t * 5 + 0];
        const float f1 = s[cur][t * 5 + 1];
        const float m  = s[cur][t * 5 + 2];
        const float d0 = s[cur][t * 5 + 3];
        const float d1 = s[cur][t * 5 + 4];

        const int idx = c * CHUNK + t;
        const float li = (float)(idx >> 6);   // row i
        const float lj = (float)(idx & 63);   // col j

        const float a  = fabsf(m);
        const float t0 = f1 * m;              // dirn0
        const float t1 = -f0 * m;             // dirn1

        den += a;
        vf0 += a * fmaf( t0, d0, li);
        vf1 += a * fmaf( t1, d0, lj);
        vs0 += a * fmaf(-t0, d1, li);
        vs1 += a * fmaf(-t1, d1, lj);
    }

    // Warp reduce 5 values
    #pragma unroll
    for (int o = 16; o; o >>= 1) {
        den += __shfl_xor_sync(0xffffffffu, den, o);
        vf0 += __shfl_xor_sync(0xffffffffu, vf0, o);
        vf1 += __shfl_xor_sync(0xffffffffu, vf1, o);
        vs0 += __shfl_xor_sync(0xffffffffu, vs0, o);
        vs1 += __shfl_xor_sync(0xffffffffu, vs1, o);
    }
    const int lane = t & 31, wid = t >> 5;
    if (lane == 0) {
        red[wid][0] = den; red[wid][1] = vf0; red[wid][2] = vf1;
        red[wid][3] = vs0; red[wid][4] = vs1;
    }
    __syncthreads();
    if (t < 5) {
        float acc = 0.f;
        #pragma unroll
        for (int w = 0; w < 8; ++w) acc += red[w][t];
        g_scratch[(b * N_PHAL + p) * 5 + t] = acc;
    }
}

// ---------------------------------------------------------------------------
// Kernel 2: keypoint epilogue. One thread per output row (b, r), r in [0,20].
// Output layout: out[b*42 + r*2 + c], shape (B, 21, 2).
// ---------------------------------------------------------------------------
__global__ void epi_kernel(float* __restrict__ out)
{
    const int tid = blockIdx.x * blockDim.x + threadIdx.x;
    if (tid >= BATCH * (N_PHAL + 1)) return;
    const int b = tid / (N_PHAL + 1);
    const int r = tid % (N_PHAL + 1);

    const float* __restrict__ sc = g_scratch + b * N_PHAL * 5;
    float* __restrict__ o = out + b * (N_PHAL + 1) * 2 + r * 2;

    if (r == 0) {
        // kp0 = mean over root phalanges of vf (where denom != 0)
        float k0 = 0.f, k1 = 0.f;
        #pragma unroll
        for (int f = 0; f < 5; ++f) {
            const int pp = 4 * f;
            const float d = sc[pp * 5 + 0];
            if (d != 0.f) {
                k0 += sc[pp * 5 + 1] / d;
                k1 += sc[pp * 5 + 2] / d;
            }
        }
        o[0] = k0 * 0.2f;
        o[1] = k1 * 0.2f;
    } else {
        const int q  = r;                       // 1..20
        const int iq = (q - 1) >> 2;
        const int jq = 4 * iq + 4 - q;
        const int pq = 4 * iq + jq;
        const int pn = min(pq + 1, N_PHAL - 1);

        const float dq  = sc[pq * 5 + 0];
        const float dqs = (dq == 0.f) ? 1.f : dq;
        const float vsx = sc[pq * 5 + 3] / dqs;
        const float vsy = sc[pq * 5 + 4] / dqs;

        if (jq == 3) {                          // tip
            o[0] = vsx;
            o[1] = vsy;
        } else {
            const float dn  = sc[pn * 5 + 0];
            const float dns = (dn == 0.f) ? 1.f : dn;
            const float vfx = sc[pn * 5 + 1] / dns;
            const float vfy = sc[pn * 5 + 2] / dns;
            o[0] = (vsx + vfx) * 0.5f;
            o[1] = (vsy + vfy) * 0.5f;
        }
    }
}

extern "C" void kernel_launch(void* const* d_in, const int* in_sizes, int n_in,
                              void* d_out, int out_size)
{
    const float* x = (const float*)d_in[0];
    float* out = (float*)d_out;

    dim3 grid(N_PHAL, BATCH);
    reduce_kernel<<<grid, 256>>>(x);

    const int n_rows = BATCH * (N_PHAL + 1);
    epi_kernel<<<(n_rows + 127) / 128, 128>>>(out);
}

// round 4
// speedup vs baseline: 1.1651x; 1.1651x over previous
#include <cuda_runtime.h>
#include <cuda_bf16.h>

// Problem constants (fixed by setup_inputs)
#define RES       64
#define N_PHAL    20
#define BATCH     256
#define N_PIX     4096
#define CH        5
#define TILE_F4   (N_PIX * CH / 4)          // 5120 float4 per (b,p) tile
#define CHUNK_PX  256                       // pixels per pipeline chunk
#define CHUNK_F4  320                       // float4 per chunk (5120 B)
#define NCHUNK_TILE 16                      // chunks per tile
#define TPB_TILES 2                         // tiles per block (contiguous)
#define NCHUNK    (NCHUNK_TILE * TPB_TILES) // 32 chunks per block
#define NBLOCKS   (BATCH * N_PHAL / TPB_TILES) // 2560
#define STAGES    4
#define OUT_ROWS  (N_PHAL + 1)              // 21

__device__ __forceinline__ unsigned smem_u32(const void* p) {
    return (unsigned)__cvta_generic_to_shared(p);
}
__device__ __forceinline__ void cp16(unsigned s, const float4* g) {
    asm volatile("cp.async.cg.shared.global [%0], [%1], 16;" :: "r"(s), "l"(g));
}
#define CP_COMMIT() asm volatile("cp.async.commit_group;")
#define CP_WAIT3()  asm volatile("cp.async.wait_group 3;")

// ---------------------------------------------------------------------------
// Zero the 256 x 21 x 2 output (it is poisoned to 0xAA before timing).
// ---------------------------------------------------------------------------
__global__ void zero_out_kernel(float* __restrict__ out)
{
    const int i = blockIdx.x * blockDim.x + threadIdx.x;
    if (i < BATCH * OUT_ROWS * 2) out[i] = 0.f;
}

// ---------------------------------------------------------------------------
// Fused reduction + keypoint scatter.
// grid = 2560 blocks x 256 threads. Block k owns 2 contiguous (b,p) tiles
// (a contiguous 160 KB byte range). 4-stage cp.async pipeline stages 5 KB
// chunks into SMEM; thread t consumes pixel t of each chunk via stride-5 LDS
// (conflict-free, gcd(5,32)==1). At each tile end: block-reduce the 5
// accumulators and atomically scatter into the output keypoint rows.
//
// Scatter map for phalanx p = 4i + j:
//   vs[p]  -> row (4i + 4 - j), weight (j==3 ? 1 : 0.5)
//   vf[p]  -> j>=1: row (4i + 5 - j), weight 0.5
//             j==0: row 0 (kp0), weight 0.2
// where vf/vs are the denom_safe-divided means (zero-mask tiles give 0
// automatically, matching the reference's where() guards).
// ---------------------------------------------------------------------------
__global__ __launch_bounds__(256) void reduce_kernel(const float* __restrict__ x,
                                                     float* __restrict__ out)
{
    __shared__ float4 s4[STAGES][CHUNK_F4];   // 4 x 5120 B
    __shared__ float  red[8][5];

    const int t    = threadIdx.x;
    const int lane = t & 31;
    const int wid  = t >> 5;

    const float4* __restrict__ base =
        (const float4*)x + (size_t)blockIdx.x * (TPB_TILES * TILE_F4);

    auto issue = [&](int c) {
        const float4* __restrict__ src = base + c * CHUNK_F4;
        float4* dst = s4[c & (STAGES - 1)];
        cp16(smem_u32(dst + t), src + t);
        if (t < CHUNK_F4 - 256)
            cp16(smem_u32(dst + 256 + t), src + 256 + t);
        CP_COMMIT();
    };

    issue(0); issue(1); issue(2);

    float den = 0.f, vf0 = 0.f, vf1 = 0.f, vs0 = 0.f, vs1 = 0.f;

    #pragma unroll 1
    for (int c = 0; c < NCHUNK; ++c) {
        // Keep exactly 4 groups in flight so wait_group(3) releases chunk c.
        if (c + 3 < NCHUNK) issue(c + 3); else CP_COMMIT();
        CP_WAIT3();
        __syncthreads();                      // chunk c fully staged

        const float* __restrict__ s = (const float*)s4[c & (STAGES - 1)];
        const float f0 = s[t * 5 + 0];
        const float f1 = s[t * 5 + 1];
        const float m  = s[t * 5 + 2];
        const float d0 = s[t * 5 + 3];
        const float d1 = s[t * 5 + 4];

        const int idx = ((c & 15) << 8) + t;  // pixel index within tile
        const float li = (float)(idx >> 6);
        const float lj = (float)(idx & 63);

        const float a  = fabsf(m);
        const float t0 = f1 * m;
        const float t1 = -f0 * m;

        den += a;
        vf0 += a * fmaf( t0, d0, li);
        vf1 += a * fmaf( t1, d0, lj);
        vs0 += a * fmaf(-t0, d1, li);
        vs1 += a * fmaf(-t1, d1, lj);

        if ((c & 15) == 15) {
            // ---- tile finished: block reduce + atomic scatter ----
            float v0 = den, v1 = vf0, v2 = vf1, v3 = vs0, v4 = vs1;
            #pragma unroll
            for (int o = 16; o; o >>= 1) {
                v0 += __shfl_xor_sync(0xffffffffu, v0, o);
                v1 += __shfl_xor_sync(0xffffffffu, v1, o);
                v2 += __shfl_xor_sync(0xffffffffu, v2, o);
                v3 += __shfl_xor_sync(0xffffffffu, v3, o);
                v4 += __shfl_xor_sync(0xffffffffu, v4, o);
            }
            if (lane == 0) {
                red[wid][0] = v0; red[wid][1] = v1; red[wid][2] = v2;
                red[wid][3] = v3; red[wid][4] = v4;
            }
            __syncthreads();
            if (t == 0) {
                float r0 = 0.f, r1 = 0.f, r2 = 0.f, r3 = 0.f, r4 = 0.f;
                #pragma unroll
                for (int w = 0; w < 8; ++w) {
                    r0 += red[w][0]; r1 += red[w][1]; r2 += red[w][2];
                    r3 += red[w][3]; r4 += red[w][4];
                }
                const float inv = (r0 == 0.f) ? 1.f : 1.f / r0;
                const float mvf0 = r1 * inv, mvf1 = r2 * inv;
                const float mvs0 = r3 * inv, mvs1 = r4 * inv;

                const int tile = blockIdx.x * TPB_TILES + (c >> 4);
                const int b = tile / N_PHAL;
                const int p = tile % N_PHAL;
                const int i = p >> 2, j = p & 3;
                float* __restrict__ ob = out + b * OUT_ROWS * 2;

                const int   r_s = 4 * i + 4 - j;
                const float w_s = (j == 3) ? 1.f : 0.5f;
                atomicAdd(ob + r_s * 2 + 0, mvs0 * w_s);
                atomicAdd(ob + r_s * 2 + 1, mvs1 * w_s);

                if (j) {
                    const int r_f = 4 * i + 5 - j;
                    atomicAdd(ob + r_f * 2 + 0, 0.5f * mvf0);
                    atomicAdd(ob + r_f * 2 + 1, 0.5f * mvf1);
                } else {
                    atomicAdd(ob + 0, 0.2f * mvf0);
                    atomicAdd(ob + 1, 0.2f * mvf1);
                }
            }
            den = vf0 = vf1 = vs0 = vs1 = 0.f;
        }
        __syncthreads();                      // stage (c&3) free for reuse
    }
}

extern "C" void kernel_launch(void* const* d_in, const int* in_sizes, int n_in,
                              void* d_out, int out_size)
{
    const float* x = (const float*)d_in[0];
    float* out = (float*)d_out;

    zero_out_kernel<<<(BATCH * OUT_ROWS * 2 + 255) / 256, 256>>>(out);
    reduce_kernel<<<NBLOCKS, 256>>>(x, out);
}

// round 7
// speedup vs baseline: 1.2436x; 1.0673x over previous
#include <cuda_runtime.h>
#include <cuda_bf16.h>
#include <cstdint>

// Problem constants (fixed by setup_inputs)
#define RES        64
#define N_PHAL     20
#define BATCH      256
#define N_TILES    (BATCH * N_PHAL)      // 5120 (b,p) tiles
#define TILE_FLT   (RES * RES * 5)       // 20480 floats = 80 KB per tile
#define CHUNK_PX   512                   // pixels per chunk
#define CHUNK_FLT  (CHUNK_PX * 5)        // 2560 floats = 10 KB
#define CHUNK_B    (CHUNK_FLT * 4)       // 10240 bytes
#define CPT        8                     // chunks per tile
#define STAGES     3
#define GRID       740                   // 148 SMs x 5 persistent blocks
#define OUT_ROWS   (N_PHAL + 1)          // 21

__device__ __forceinline__ unsigned smem_u32(const void* p) {
    return (unsigned)__cvta_generic_to_shared(p);
}

__device__ __forceinline__ void mbar_init(unsigned mbar, unsigned count) {
    asm volatile("mbarrier.init.shared.b64 [%0], %1;" :: "r"(mbar), "r"(count) : "memory");
}
__device__ __forceinline__ void mbar_expect_tx(unsigned mbar, unsigned bytes) {
    asm volatile("mbarrier.arrive.expect_tx.shared.b64 _, [%0], %1;"
                 :: "r"(mbar), "r"(bytes) : "memory");
}
__device__ __forceinline__ void mbar_wait(unsigned mbar, unsigned parity) {
    asm volatile(
        "{\n\t"
        ".reg .pred P;\n\t"
        "W%=:\n\t"
        "mbarrier.try_wait.parity.acquire.cta.shared::cta.b64 P, [%0], %1, 0x989680;\n\t"
        "@P bra D%=;\n\t"
        "bra W%=;\n\t"
        "D%=:\n\t"
        "}"
        :: "r"(mbar), "r"(parity) : "memory");
}
__device__ __forceinline__ void bulk_cp(unsigned dst, const void* src, unsigned bytes,
                                        unsigned mbar) {
    asm volatile(
        "cp.async.bulk.shared::cta.global.mbarrier::complete_tx::bytes [%0], [%1], %2, [%3];"
        :: "r"(dst), "l"(src), "r"(bytes), "r"(mbar) : "memory");
}
__device__ __forceinline__ void fence_async_shared() {
    asm volatile("fence.proxy.async.shared::cta;" ::: "memory");
}

// ---------------------------------------------------------------------------
// Zero the 256 x 21 x 2 output (poisoned to 0xAA before timing).
// ---------------------------------------------------------------------------
__global__ void zero_out_kernel(float* __restrict__ out)
{
    const int i = blockIdx.x * blockDim.x + threadIdx.x;
    if (i < BATCH * OUT_ROWS * 2) out[i] = 0.f;
}

// ---------------------------------------------------------------------------
// Persistent fused reduction + keypoint scatter.
// Block k owns tiles k, k+GRID, k+2*GRID, ... (6-7 tiles each, 80 KB
// contiguous per tile). Flat chunk stream (8 chunks/tile, 10 KB each) runs
// through a 3-stage TMA-bulk + mbarrier pipeline; one elected thread moves
// each chunk with a single cp.async.bulk. 256 threads consume 2 pixels each
// via stride-5 LDS (conflict-free, gcd(5,32)==1). At tile end: block-reduce
// 5 accumulators and atomically scatter into the output keypoint rows.
//
// Scatter map for phalanx p = 4i + j (verified in R4, rel_err 8.9e-8):
//   vs[p] -> row 4i+4-j, weight (j==3 ? 1 : 0.5)
//   vf[p] -> j>=1: row 4i+5-j, weight 0.5 ; j==0: row 0, weight 0.2
// ---------------------------------------------------------------------------
__global__ __launch_bounds__(256) void reduce_kernel(const float* __restrict__ x,
                                                     float* __restrict__ out)
{
    __shared__ __align__(128) float sbuf[STAGES][CHUNK_FLT];  // 3 x 10 KB
    __shared__ __align__(8) unsigned long long mbar_s[STAGES];
    __shared__ float red[8][5];

    const int t    = threadIdx.x;
    const int lane = t & 31;
    const int wid  = t >> 5;
    const int blk  = blockIdx.x;

    const int ntiles = (N_TILES - blk + GRID - 1) / GRID;   // 6 or 7
    const int NC     = ntiles * CPT;

    const unsigned mb0 = smem_u32(&mbar_s[0]);

    if (t == 0) {
        #pragma unroll
        for (int s = 0; s < STAGES; ++s) mbar_init(mb0 + 8u * s, 1u);
        fence_async_shared();
    }
    __syncthreads();

    auto src_of = [&](int cc) -> const float* {
        const int tile = blk + (cc >> 3) * GRID;
        return x + (size_t)tile * TILE_FLT + (size_t)(cc & 7) * CHUNK_FLT;
    };
    auto issue = [&](int cc) {
        const unsigned mb = mb0 + 8u * (unsigned)(cc % STAGES);
        mbar_expect_tx(mb, CHUNK_B);
        bulk_cp(smem_u32(sbuf[cc % STAGES]), src_of(cc), CHUNK_B, mb);
    };

    if (t == 0) { issue(0); issue(1); issue(2); }

    const float ljf = (float)(t & 63);
    const int   lib = t >> 6;                     // row base of pixel t

    float den = 0.f, vf0 = 0.f, vf1 = 0.f, vs0 = 0.f, vs1 = 0.f;

    #pragma unroll 1
    for (int cc = 0; cc < NC; ++cc) {
        const int      stg = cc % STAGES;
        const unsigned par = (unsigned)((cc / STAGES) & 1);
        mbar_wait(mb0 + 8u * stg, par);

        const float* __restrict__ sp = sbuf[stg];
        const float libase = (float)(((cc & 7) << 3) + lib);

        #pragma unroll
        for (int k = 0; k < 2; ++k) {
            const float* __restrict__ q = sp + (t + (k << 8)) * 5;
            const float f0 = q[0];
            const float f1 = q[1];
            const float m  = q[2];
            const float d0 = q[3];
            const float d1 = q[4];

            const float li = libase + (float)(k << 2);
            const float a  = fabsf(m);
            const float t0 = f1 * m;
            const float t1 = -f0 * m;

            den += a;
            vf0 += a * fmaf( t0, d0, li);
            vf1 += a * fmaf( t1, d0, ljf);
            vs0 += a * fmaf(-t0, d1, li);
            vs1 += a * fmaf(-t1, d1, ljf);
        }

        const bool tile_end = ((cc & 7) == 7);
        if (tile_end) {
            float v0 = den, v1 = vf0, v2 = vf1, v3 = vs0, v4 = vs1;
            #pragma unroll
            for (int o = 16; o; o >>= 1) {
                v0 += __shfl_xor_sync(0xffffffffu, v0, o);
                v1 += __shfl_xor_sync(0xffffffffu, v1, o);
                v2 += __shfl_xor_sync(0xffffffffu, v2, o);
                v3 += __shfl_xor_sync(0xffffffffu, v3, o);
                v4 += __shfl_xor_sync(0xffffffffu, v4, o);
            }
            if (lane == 0) {
                red[wid][0] = v0; red[wid][1] = v1; red[wid][2] = v2;
                red[wid][3] = v3; red[wid][4] = v4;
            }
            den = vf0 = vf1 = vs0 = vs1 = 0.f;
        }

        __syncthreads();   // stage consumed by all; red[] (if any) published

        if (t == 0) {
            if (cc + STAGES < NC) {
                fence_async_shared();
                issue(cc + STAGES);
            }
            if (tile_end) {
                float r0 = 0.f, r1 = 0.f, r2 = 0.f, r3 = 0.f, r4 = 0.f;
                #pragma unroll
                for (int w = 0; w < 8; ++w) {
                    r0 += red[w][0]; r1 += red[w][1]; r2 += red[w][2];
                    r3 += red[w][3]; r4 += red[w][4];
                }
                const float inv  = (r0 == 0.f) ? 1.f : 1.f / r0;
                const float mvf0 = r1 * inv, mvf1 = r2 * inv;
                const float mvs0 = r3 * inv, mvs1 = r4 * inv;

                const int tile = blk + (cc >> 3) * GRID;
                const int b = tile / N_PHAL;
                const int p = tile % N_PHAL;
                const int i = p >> 2, j = p & 3;
                float* __restrict__ ob = out + b * OUT_ROWS * 2;

                const int   r_s = 4 * i + 4 - j;
                const float w_s = (j == 3) ? 1.f : 0.5f;
                atomicAdd(ob + r_s * 2 + 0, mvs0 * w_s);
                atomicAdd(ob + r_s * 2 + 1, mvs1 * w_s);

                if (j) {
                    const int r_f = 4 * i + 5 - j;
                    atomicAdd(ob + r_f * 2 + 0, 0.5f * mvf0);
                    atomicAdd(ob + r_f * 2 + 1, 0.5f * mvf1);
                } else {
                    atomicAdd(ob + 0, 0.2f * mvf0);
                    atomicAdd(ob + 1, 0.2f * mvf1);
                }
            }
        }
    }
}

extern "C" void kernel_launch(void* const* d_in, const int* in_sizes, int n_in,
                              void* d_out, int out_size)
{
    const float* x = (const float*)d_in[0];
    float* out = (float*)d_out;

    zero_out_kernel<<<(BATCH * OUT_ROWS * 2 + 255) / 256, 256>>>(out);
    reduce_kernel<<<GRID, 256>>>(x, out);
}